// round 9
// baseline (speedup 1.0000x reference)
#include <cuda_runtime.h>
#include <cuda_fp16.h>
#include <cstdint>

#define MOD_SCALE 0.04419417382415922f   /* 1/sqrt(512) */
#define CONV_SCALE 0.014731391274719739f /* 1/sqrt(512*9) */

// ---------------- device scratch ----------------
__device__ __align__(16) __half g_Xs[16 * 64 * 64 * 512]; // NHWC x*s fp16
__device__ __align__(16) __half g_Wh[9 * 512 * 512];      // [tap][co][ci] fp16
__device__ float  g_W2[512 * 512];
__device__ float  g_s[16 * 512];
__device__ float  g_alpha[16 * 512];

// ---------------- fused kernel A: mod (blocks 0-1023) + weight prep (1024-2047) ----------------
__global__ void prepA_kernel(const float* __restrict__ style,
                             const float* __restrict__ mw,
                             const float* __restrict__ bias,
                             const float* __restrict__ weight) {
    if (blockIdx.x < 1024) {
        int warp = (blockIdx.x * 256 + threadIdx.x) >> 5;
        int lane = threadIdx.x & 31;
        int b = warp >> 9, ci = warp & 511;
        float sum = 0.f;
        const float* st = style + b * 512;
        const float* w  = mw + ci * 512;
        for (int d = lane; d < 512; d += 32) sum += st[d] * w[d];
        #pragma unroll
        for (int off = 16; off > 0; off >>= 1) sum += __shfl_xor_sync(0xffffffffu, sum, off);
        if (lane == 0) g_s[b * 512 + ci] = sum * MOD_SCALE + bias[ci];
    } else {
        int idx = (blockIdx.x - 1024) * 256 + threadIdx.x;  // co*512+ci
        const float* w = weight + (size_t)idx * 9;
        float s2 = 0.f;
        #pragma unroll
        for (int k = 0; k < 9; k++) {
            float v = w[k];
            s2 += v * v;
            g_Wh[k * (512 * 512) + idx] = __float2half(v);
        }
        g_W2[idx] = s2;
    }
}

// ---------------- fused kernel B: demod alpha (blocks 0-1023) + Xs build (1024+) ----------------
__global__ void prepB_kernel(const float* __restrict__ x) {
    __shared__ float sm[32][65];
    __shared__ float ss[32];
    if (blockIdx.x < 1024) {
        int warp = (blockIdx.x * 256 + threadIdx.x) >> 5;
        int lane = threadIdx.x & 31;
        int b = warp >> 9, co = warp & 511;
        float sum = 0.f;
        const float* w2 = g_W2 + co * 512;
        const float* sv = g_s + b * 512;
        for (int ci = lane; ci < 512; ci += 32) {
            float s = sv[ci];
            sum += w2[ci] * s * s;
        }
        #pragma unroll
        for (int off = 16; off > 0; off >>= 1) sum += __shfl_xor_sync(0xffffffffu, sum, off);
        if (lane == 0)
            g_alpha[b * 512 + co] = CONV_SCALE / sqrtf(CONV_SCALE * CONV_SCALE * sum + 1e-8f);
    } else {
        int id = blockIdx.x - 1024;                 // 16384 blocks
        int ci0 = (id & 15) * 32, y = (id >> 4) & 63, b = id >> 10;
        int tid = threadIdx.x;
        if (tid < 32) ss[tid] = g_s[b * 512 + ci0 + tid];
        {
            int i = tid >> 3, v = tid & 7;
            const float4* src = reinterpret_cast<const float4*>(
                x + (((size_t)(b * 512 + ci0 + i) * 64 + y) * 64));
            float4 f0 = src[v * 2], f1 = src[v * 2 + 1];
            int c = v * 8;
            sm[i][c+0]=f0.x; sm[i][c+1]=f0.y; sm[i][c+2]=f0.z; sm[i][c+3]=f0.w;
            sm[i][c+4]=f1.x; sm[i][c+5]=f1.y; sm[i][c+6]=f1.z; sm[i][c+7]=f1.w;
        }
        __syncthreads();
        {
            int xc = tid >> 2, g = tid & 3;
            union { __half h[8]; uint4 u; } pk;
            #pragma unroll
            for (int j = 0; j < 8; j++)
                pk.h[j] = __float2half(sm[g * 8 + j][xc] * ss[g * 8 + j]);
            *reinterpret_cast<uint4*>(
                g_Xs + ((size_t)((b * 64 + y) * 64 + xc) * 512) + ci0 + g * 8) = pk.u;
        }
    }
}

// ================= conv kernel: warp-specialized producer/consumer =================
// CTA: 64 co x 512 px (8 rows); 10 warps = 8 consumers (2m x 4n) + 2 producers.
// 16 stages of kc=32 ci, 2-deep smem ring. NO __syncthreads in the main loop:
//   producers (warp 8: X, warp 9: W) cp.async + cp.async.mbarrier.arrive.noinc -> full[buf]
//   consumers try_wait full[buf], run mma stage, arrive empty[buf] (1/warp).

#define XB_HALFS (660 * 40)   /* 26400 -> 52800 B */
#define WB_HALFS (576 * 40)   /* 23040 -> 46080 B */
#define XB_BYTES (XB_HALFS * 2)
#define WB_BYTES (WB_HALFS * 2)
#define SMEM_BYTES (2 * XB_BYTES + 2 * WB_BYTES)   /* 197760 */

__device__ __forceinline__ void cp16(uint32_t dst, const void* src, int sz) {
    asm volatile("cp.async.cg.shared.global [%0], [%1], 16, %2;"
                 :: "r"(dst), "l"(src), "r"(sz) : "memory");
}
__device__ __forceinline__ void ldsm4(uint32_t r[4], uint32_t addr) {
    asm volatile("ldmatrix.sync.aligned.m8n8.x4.shared.b16 {%0,%1,%2,%3}, [%4];"
                 : "=r"(r[0]), "=r"(r[1]), "=r"(r[2]), "=r"(r[3]) : "r"(addr));
}
__device__ __forceinline__ void mma_f16(float acc[4], const uint32_t a[4], const uint32_t b2[2]) {
    asm volatile(
        "mma.sync.aligned.m16n8k16.row.col.f32.f16.f16.f32 "
        "{%0,%1,%2,%3}, {%4,%5,%6,%7}, {%8,%9}, {%0,%1,%2,%3};\n"
        : "+f"(acc[0]), "+f"(acc[1]), "+f"(acc[2]), "+f"(acc[3])
        : "r"(a[0]), "r"(a[1]), "r"(a[2]), "r"(a[3]), "r"(b2[0]), "r"(b2[1]));
}
__device__ __forceinline__ void mbar_init(uint32_t a, uint32_t cnt) {
    asm volatile("mbarrier.init.shared.b64 [%0], %1;" :: "r"(a), "r"(cnt) : "memory");
}
__device__ __forceinline__ void mbar_arrive(uint32_t a) {
    asm volatile("mbarrier.arrive.shared.b64 _, [%0];" :: "r"(a) : "memory");
}
__device__ __forceinline__ void mbar_wait(uint32_t a, uint32_t ph) {
    asm volatile("{\n\t.reg .pred P;\n\tWL%=:\n\t"
                 "mbarrier.try_wait.parity.acquire.cta.shared::cta.b64 P, [%0], %1, 0x989680;\n\t"
                 "@P bra.uni WD%=;\n\tbra.uni WL%=;\n\tWD%=:\n\t}"
                 :: "r"(a), "r"(ph) : "memory");
}
__device__ __forceinline__ void cpasync_mbar_arrive(uint32_t a) {
    asm volatile("cp.async.mbarrier.arrive.noinc.shared.b64 [%0];" :: "r"(a) : "memory");
}

__global__ void __launch_bounds__(320, 1) conv_kernel(float* __restrict__ out) {
    extern __shared__ __align__(16) __half sh[];
    __shared__ __align__(8) uint64_t mb[4];   // full0, full1, empty0, empty1
    const uint32_t sbase = (uint32_t)__cvta_generic_to_shared(sh);
    const uint32_t mbase = (uint32_t)__cvta_generic_to_shared(mb);
    const uint32_t xoff[2] = { sbase, sbase + XB_BYTES };
    const uint32_t woff[2] = { sbase + 2 * XB_BYTES, sbase + 2 * XB_BYTES + WB_BYTES };

    const int tid = threadIdx.x, lane = tid & 31, warp = tid >> 5;
    const int b = blockIdx.z, co0 = blockIdx.y * 64, y0 = blockIdx.x * 8;

    if (tid == 0) {
        mbar_init(mbase + 0, 64);   // full0: 2 producer warps x 32 threads
        mbar_init(mbase + 8, 64);   // full1
        mbar_init(mbase + 16, 8);   // empty0: 8 consumer warps
        mbar_init(mbase + 24, 8);   // empty1
    }
    __syncthreads();

    if (warp == 8) {
        // -------- producer: X tile (660 px x 32 ci; 2640 cp of 16B per stage) --------
        int eph0 = 0, eph1 = 0;
        const int v = lane & 3;
        for (int s = 0; s < 16; s++) {
            const int buf = s & 1;
            if (s >= 2) {
                if (buf) { mbar_wait(mbase + 24, eph1); eph1 ^= 1; }
                else     { mbar_wait(mbase + 16, eph0); eph0 ^= 1; }
            }
            const uint32_t xb = xoff[buf];
            const int ofs = s * 32;
            for (int i = lane; i < 2640; i += 32) {
                int p = i >> 2;
                int r = p / 66, c = p - r * 66;
                int iy = y0 - 1 + r, ix = c - 1;
                int ok = (iy >= 0 && iy < 64 && ix >= 0 && ix < 64) ? 16 : 0;
                int iyc = iy < 0 ? 0 : (iy > 63 ? 63 : iy);
                int ixc = ix < 0 ? 0 : (ix > 63 ? 63 : ix);
                const __half* src = g_Xs + ((size_t)((b * 64 + iyc) * 64 + ixc) * 512 + ofs + v * 8);
                cp16(xb + (uint32_t)(p * 40 + v * 8) * 2, src, ok);
            }
            cpasync_mbar_arrive(mbase + buf * 8);
        }
        return;
    }
    if (warp == 9) {
        // -------- producer: W tile (9 taps x 64 co x 32 ci; 2304 cp per stage) --------
        int eph0 = 0, eph1 = 0;
        const int v = lane & 3;
        for (int s = 0; s < 16; s++) {
            const int buf = s & 1;
            if (s >= 2) {
                if (buf) { mbar_wait(mbase + 24, eph1); eph1 ^= 1; }
                else     { mbar_wait(mbase + 16, eph0); eph0 ^= 1; }
            }
            const uint32_t wb = woff[buf];
            const int ofs = s * 32;
            for (int j = lane; j < 2304; j += 32) {
                int row = j >> 2;               // tap*64 + co_l
                int tap = row >> 6, co_l = row & 63;
                const __half* src = g_Wh + ((size_t)(tap * 512 + co0 + co_l) * 512 + ofs + v * 8);
                cp16(wb + (uint32_t)(row * 40 + v * 8) * 2, src, 16);
            }
            cpasync_mbar_arrive(mbase + buf * 8);
        }
        return;
    }

    // ================= consumers: warps 0-7 =================
    const int wm = warp & 1, wn = warp >> 1;

    const int l15 = ((lane >> 3) & 1) * 8 + (lane & 7);
    const int aK  = (lane >> 4) * 8;
    uint32_t aBase[2];
    #pragma unroll
    for (int mf = 0; mf < 2; mf++)
        aBase[mf] = (uint32_t)(((wm * 32 + mf * 16 + l15) * 40 + aK) * 2);
    const int nloc = ((lane >> 4) & 1) * 8 + (lane & 7);
    const int bK   = ((lane >> 3) & 1) * 8;
    uint32_t bBase[8];
    #pragma unroll
    for (int nfp = 0; nfp < 8; nfp++) {
        int px = wn * 128 + nfp * 16 + nloc;
        bBase[nfp] = (uint32_t)((((px >> 6) * 66 + (px & 63)) * 40 + bK) * 2);
    }

    float acc[2][16][4];
    #pragma unroll
    for (int mf = 0; mf < 2; mf++)
        #pragma unroll
        for (int nf = 0; nf < 16; nf++)
            #pragma unroll
            for (int i = 0; i < 4; i++) acc[mf][nf][i] = 0.f;

    int fph0 = 0, fph1 = 0;
    for (int s = 0; s < 16; s++) {
        const int buf = s & 1;
        if (buf) { mbar_wait(mbase + 8, fph1); fph1 ^= 1; }
        else     { mbar_wait(mbase + 0, fph0); fph0 ^= 1; }

        const uint32_t xB = xoff[buf], wB = woff[buf];

        #define AOFS(t, h) (wB + aBase[h] + (uint32_t)(((t) >> 1) * 5120 + ((t) & 1) * 32))
        #define BOFS(t, nfp) (xB + bBase[nfp] + \
            (uint32_t)(((((t) >> 1) / 3) * 66 + (((t) >> 1) % 3)) * 80 + ((t) & 1) * 32))

        uint32_t aa[2][2][4];
        uint32_t bb[2][4];
        ldsm4(aa[0][0], AOFS(0, 0));
        ldsm4(aa[0][1], AOFS(0, 1));
        ldsm4(bb[0], BOFS(0, 0));

        #pragma unroll
        for (int t = 0; t < 18; t++) {
            const int ct = t & 1, nt = ct ^ 1;
            if (t < 17) {
                ldsm4(aa[nt][0], AOFS(t + 1, 0));
                ldsm4(aa[nt][1], AOFS(t + 1, 1));
            }
            #pragma unroll
            for (int nfp = 0; nfp < 8; nfp++) {
                const int cb = nfp & 1, nb = cb ^ 1;
                if (nfp < 7)        ldsm4(bb[nb], BOFS(t, nfp + 1));
                else if (t < 17)    ldsm4(bb[nb], BOFS(t + 1, 0));
                mma_f16(acc[0][2 * nfp],     aa[ct][0], bb[cb]);
                mma_f16(acc[0][2 * nfp + 1], aa[ct][0], bb[cb] + 2);
                mma_f16(acc[1][2 * nfp],     aa[ct][1], bb[cb]);
                mma_f16(acc[1][2 * nfp + 1], aa[ct][1], bb[cb] + 2);
            }
        }
        #undef AOFS
        #undef BOFS

        if (lane == 0) mbar_arrive(mbase + 16 + buf * 8);
    }

    // ---- epilogue: out = alpha * acc, NCHW fp32 ----
    #pragma unroll
    for (int mf = 0; mf < 2; mf++) {
        int cobase = co0 + wm * 32 + mf * 16 + (lane >> 2);
        float al0 = g_alpha[b * 512 + cobase];
        float al1 = g_alpha[b * 512 + cobase + 8];
        float* o0 = out + ((size_t)(b * 512 + cobase)) * 4096;
        float* o1 = o0 + 8 * 4096;
        #pragma unroll
        for (int nf = 0; nf < 16; nf++) {
            int px = wn * 128 + nf * 8 + (lane & 3) * 2;
            int ofs = (y0 + (px >> 6)) * 64 + (px & 63);
            *reinterpret_cast<float2*>(o0 + ofs) =
                make_float2(al0 * acc[mf][nf][0], al0 * acc[mf][nf][1]);
            *reinterpret_cast<float2*>(o1 + ofs) =
                make_float2(al1 * acc[mf][nf][2], al1 * acc[mf][nf][3]);
        }
    }
}

// ---------------- launch ----------------
extern "C" void kernel_launch(void* const* d_in, const int* in_sizes, int n_in,
                              void* d_out, int out_size) {
    const float* x     = (const float*)d_in[0];
    const float* style = (const float*)d_in[1];
    const float* weight= (const float*)d_in[2];
    const float* mw    = (const float*)d_in[3];
    const float* mbias = (const float*)d_in[4];
    float* out = (float*)d_out;
    (void)in_sizes; (void)n_in; (void)out_size;

    cudaFuncSetAttribute(conv_kernel, cudaFuncAttributeMaxDynamicSharedMemorySize, SMEM_BYTES);

    prepA_kernel<<<2048, 256>>>(style, mw, mbias, weight);
    prepB_kernel<<<1024 + 16384, 256>>>(x);
    conv_kernel<<<dim3(8, 8, 16), 320, SMEM_BYTES>>>(out);
}

// round 10
// speedup vs baseline: 1.0523x; 1.0523x over previous
#include <cuda_runtime.h>
#include <cuda_fp16.h>
#include <cstdint>

#define MOD_SCALE 0.04419417382415922f   /* 1/sqrt(512) */
#define CONV_SCALE 0.014731391274719739f /* 1/sqrt(512*9) */

// ---------------- device scratch ----------------
__device__ __align__(16) __half g_Xs[16 * 64 * 64 * 512]; // NHWC x*s fp16
__device__ __align__(16) __half g_Wh[9 * 512 * 512];      // [tap][co][ci] fp16
__device__ float  g_W2[512 * 512];
__device__ float  g_s[16 * 512];
__device__ float  g_alpha[16 * 512];

// ---------------- fused kernel A: mod (blocks 0-1023) + weight prep (1024-2047) ----------------
__global__ void prepA_kernel(const float* __restrict__ style,
                             const float* __restrict__ mw,
                             const float* __restrict__ bias,
                             const float* __restrict__ weight) {
    if (blockIdx.x < 1024) {
        int warp = (blockIdx.x * 256 + threadIdx.x) >> 5;
        int lane = threadIdx.x & 31;
        int b = warp >> 9, ci = warp & 511;
        float sum = 0.f;
        const float* st = style + b * 512;
        const float* w  = mw + ci * 512;
        for (int d = lane; d < 512; d += 32) sum += st[d] * w[d];
        #pragma unroll
        for (int off = 16; off > 0; off >>= 1) sum += __shfl_xor_sync(0xffffffffu, sum, off);
        if (lane == 0) g_s[b * 512 + ci] = sum * MOD_SCALE + bias[ci];
    } else {
        int idx = (blockIdx.x - 1024) * 256 + threadIdx.x;  // co*512+ci
        const float* w = weight + (size_t)idx * 9;
        float s2 = 0.f;
        #pragma unroll
        for (int k = 0; k < 9; k++) {
            float v = w[k];
            s2 += v * v;
            g_Wh[k * (512 * 512) + idx] = __float2half(v);
        }
        g_W2[idx] = s2;
    }
}

// ---------------- fused kernel B: demod alpha (blocks 0-1023) + Xs build (1024+) ----------------
// Xs part: each block transposes 32 ci x 64 x for TWO y-rows (MLP 4, one sync).
__global__ void prepB_kernel(const float* __restrict__ x) {
    __shared__ float sm[2][32][65];
    __shared__ float ss[32];
    if (blockIdx.x < 1024) {
        int warp = (blockIdx.x * 256 + threadIdx.x) >> 5;
        int lane = threadIdx.x & 31;
        int b = warp >> 9, co = warp & 511;
        float sum = 0.f;
        const float* w2 = g_W2 + co * 512;
        const float* sv = g_s + b * 512;
        for (int ci = lane; ci < 512; ci += 32) {
            float s = sv[ci];
            sum += w2[ci] * s * s;
        }
        #pragma unroll
        for (int off = 16; off > 0; off >>= 1) sum += __shfl_xor_sync(0xffffffffu, sum, off);
        if (lane == 0)
            g_alpha[b * 512 + co] = CONV_SCALE / sqrtf(CONV_SCALE * CONV_SCALE * sum + 1e-8f);
    } else {
        int id = blockIdx.x - 1024;                 // 8192 blocks
        int ci0 = (id & 15) * 32, y0 = ((id >> 4) & 31) * 2, b = id >> 9;
        int tid = threadIdx.x;
        if (tid < 32) ss[tid] = g_s[b * 512 + ci0 + tid];
        {
            int i = tid >> 3, v = tid & 7;          // ci-local, float4 pair index
            const float4* s0 = reinterpret_cast<const float4*>(
                x + (((size_t)(b * 512 + ci0 + i) * 64 + y0) * 64));
            const float4* s1 = reinterpret_cast<const float4*>(
                x + (((size_t)(b * 512 + ci0 + i) * 64 + y0 + 1) * 64));
            float4 a0 = s0[v * 2], a1 = s0[v * 2 + 1];   // 4 independent loads (MLP 4)
            float4 c0 = s1[v * 2], c1 = s1[v * 2 + 1];
            int c = v * 8;
            sm[0][i][c+0]=a0.x; sm[0][i][c+1]=a0.y; sm[0][i][c+2]=a0.z; sm[0][i][c+3]=a0.w;
            sm[0][i][c+4]=a1.x; sm[0][i][c+5]=a1.y; sm[0][i][c+6]=a1.z; sm[0][i][c+7]=a1.w;
            sm[1][i][c+0]=c0.x; sm[1][i][c+1]=c0.y; sm[1][i][c+2]=c0.z; sm[1][i][c+3]=c0.w;
            sm[1][i][c+4]=c1.x; sm[1][i][c+5]=c1.y; sm[1][i][c+6]=c1.z; sm[1][i][c+7]=c1.w;
        }
        __syncthreads();
        {
            int xc = tid >> 2, g = tid & 3;         // col, ci-octet
            union { __half h[8]; uint4 u; } p0, p1;
            #pragma unroll
            for (int j = 0; j < 8; j++) {
                float s = ss[g * 8 + j];
                p0.h[j] = __float2half(sm[0][g * 8 + j][xc] * s);
                p1.h[j] = __float2half(sm[1][g * 8 + j][xc] * s);
            }
            size_t base = (size_t)((b * 64 + y0) * 64 + xc) * 512 + ci0 + g * 8;
            *reinterpret_cast<uint4*>(g_Xs + base) = p0.u;
            *reinterpret_cast<uint4*>(g_Xs + base + 64 * 512) = p1.u;
        }
    }
}

// ================= conv kernel: R8 (best) — tiling + software-pipelined operands =================
// CTA: 64 co x 512 px (8 rows). 8 warps = 2 m x 4 n. 16 stages of kc=32 ci.
// X: 660 px (10x66 halo), rows padded to 40 halfs (80B). W: 9 taps x 64 co, 40-half rows.

#define XB_HALFS (660 * 40)   /* 26400 -> 52800 B */
#define WB_HALFS (576 * 40)   /* 23040 -> 46080 B */
#define XB_BYTES (XB_HALFS * 2)
#define WB_BYTES (WB_HALFS * 2)
#define SMEM_BYTES (2 * XB_BYTES + 2 * WB_BYTES)   /* 197760 */

__device__ __forceinline__ void cp16(uint32_t dst, const void* src, int sz) {
    asm volatile("cp.async.cg.shared.global [%0], [%1], 16, %2;"
                 :: "r"(dst), "l"(src), "r"(sz) : "memory");
}
__device__ __forceinline__ void cp_commit() {
    asm volatile("cp.async.commit_group;" ::: "memory");
}
__device__ __forceinline__ void ldsm4(uint32_t r[4], uint32_t addr) {
    asm volatile("ldmatrix.sync.aligned.m8n8.x4.shared.b16 {%0,%1,%2,%3}, [%4];"
                 : "=r"(r[0]), "=r"(r[1]), "=r"(r[2]), "=r"(r[3]) : "r"(addr));
}
__device__ __forceinline__ void mma_f16(float acc[4], const uint32_t a[4], const uint32_t b2[2]) {
    asm volatile(
        "mma.sync.aligned.m16n8k16.row.col.f32.f16.f16.f32 "
        "{%0,%1,%2,%3}, {%4,%5,%6,%7}, {%8,%9}, {%0,%1,%2,%3};\n"
        : "+f"(acc[0]), "+f"(acc[1]), "+f"(acc[2]), "+f"(acc[3])
        : "r"(a[0]), "r"(a[1]), "r"(a[2]), "r"(a[3]), "r"(b2[0]), "r"(b2[1]));
}

__device__ __forceinline__ void fill_stage(uint32_t xb, uint32_t wb,
                                           int b, int y0, int co0, int kc, int tid) {
    #pragma unroll
    for (int it = 0; it < 11; it++) {
        int i = tid + it * 256;
        if (i < 2640) {
            int v = i & 3, p = i >> 2;
            int r = p / 66, c = p - r * 66;
            int iy = y0 - 1 + r, ix = c - 1;
            int ok = (iy >= 0 && iy < 64 && ix >= 0 && ix < 64) ? 16 : 0;
            int iyc = iy < 0 ? 0 : (iy > 63 ? 63 : iy);
            int ixc = ix < 0 ? 0 : (ix > 63 ? 63 : ix);
            const __half* src = g_Xs + ((size_t)((b * 64 + iyc) * 64 + ixc) * 512 + kc * 32 + v * 8);
            cp16(xb + (uint32_t)(p * 40 + v * 8) * 2, src, ok);
        }
    }
    #pragma unroll
    for (int it = 0; it < 9; it++) {
        int i = tid + it * 256;
        int v = i & 3, row = i >> 2;
        int tap = row >> 6, co_l = row & 63;
        const __half* src = g_Wh + ((size_t)(tap * 512 + co0 + co_l) * 512 + kc * 32 + v * 8);
        cp16(wb + (uint32_t)(row * 40 + v * 8) * 2, src, 16);
    }
    cp_commit();
}

__global__ void __launch_bounds__(256, 1) conv_kernel(float* __restrict__ out) {
    extern __shared__ __align__(16) __half sh[];
    const uint32_t sbase = (uint32_t)__cvta_generic_to_shared(sh);
    const uint32_t xoff[2] = { sbase, sbase + XB_BYTES };
    const uint32_t woff[2] = { sbase + 2 * XB_BYTES, sbase + 2 * XB_BYTES + WB_BYTES };

    const int tid = threadIdx.x, lane = tid & 31, warp = tid >> 5;
    const int wm = warp & 1, wn = warp >> 1;
    const int b = blockIdx.z, co0 = blockIdx.y * 64, y0 = blockIdx.x * 8;

    const int l15 = ((lane >> 3) & 1) * 8 + (lane & 7);
    const int aK  = (lane >> 4) * 8;
    uint32_t aBase[2];
    #pragma unroll
    for (int mf = 0; mf < 2; mf++)
        aBase[mf] = (uint32_t)(((wm * 32 + mf * 16 + l15) * 40 + aK) * 2);
    const int nloc = ((lane >> 4) & 1) * 8 + (lane & 7);
    const int bK   = ((lane >> 3) & 1) * 8;
    uint32_t bBase[8];
    #pragma unroll
    for (int nfp = 0; nfp < 8; nfp++) {
        int px = wn * 128 + nfp * 16 + nloc;
        bBase[nfp] = (uint32_t)((((px >> 6) * 66 + (px & 63)) * 40 + bK) * 2);
    }

    float acc[2][16][4];
    #pragma unroll
    for (int mf = 0; mf < 2; mf++)
        #pragma unroll
        for (int nf = 0; nf < 16; nf++)
            #pragma unroll
            for (int i = 0; i < 4; i++) acc[mf][nf][i] = 0.f;

    fill_stage(xoff[0], woff[0], b, y0, co0, 0, tid);
    fill_stage(xoff[1], woff[1], b, y0, co0, 1, tid);

    for (int s = 0; s < 16; s++) {
        if (s < 15) asm volatile("cp.async.wait_group 1;" ::: "memory");
        else        asm volatile("cp.async.wait_group 0;" ::: "memory");
        __syncthreads();

        const uint32_t xB = xoff[s & 1], wB = woff[s & 1];

        #define AOFS(t, h) (wB + aBase[h] + (uint32_t)(((t) >> 1) * 5120 + ((t) & 1) * 32))
        #define BOFS(t, nfp) (xB + bBase[nfp] + \
            (uint32_t)(((((t) >> 1) / 3) * 66 + (((t) >> 1) % 3)) * 80 + ((t) & 1) * 32))

        uint32_t aa[2][2][4];
        uint32_t bb[2][4];
        ldsm4(aa[0][0], AOFS(0, 0));
        ldsm4(aa[0][1], AOFS(0, 1));
        ldsm4(bb[0], BOFS(0, 0));

        #pragma unroll
        for (int t = 0; t < 18; t++) {
            const int ct = t & 1, nt = ct ^ 1;
            if (t < 17) {
                ldsm4(aa[nt][0], AOFS(t + 1, 0));
                ldsm4(aa[nt][1], AOFS(t + 1, 1));
            }
            #pragma unroll
            for (int nfp = 0; nfp < 8; nfp++) {
                const int cb = nfp & 1, nb = cb ^ 1;
                if (nfp < 7)        ldsm4(bb[nb], BOFS(t, nfp + 1));
                else if (t < 17)    ldsm4(bb[nb], BOFS(t + 1, 0));
                mma_f16(acc[0][2 * nfp],     aa[ct][0], bb[cb]);
                mma_f16(acc[0][2 * nfp + 1], aa[ct][0], bb[cb] + 2);
                mma_f16(acc[1][2 * nfp],     aa[ct][1], bb[cb]);
                mma_f16(acc[1][2 * nfp + 1], aa[ct][1], bb[cb] + 2);
            }
        }
        #undef AOFS
        #undef BOFS

        __syncthreads();
        if (s + 2 < 16) fill_stage(xoff[s & 1], woff[s & 1], b, y0, co0, s + 2, tid);
    }

    // ---- epilogue: out = alpha * acc, NCHW fp32 ----
    #pragma unroll
    for (int mf = 0; mf < 2; mf++) {
        int cobase = co0 + wm * 32 + mf * 16 + (lane >> 2);
        float al0 = g_alpha[b * 512 + cobase];
        float al1 = g_alpha[b * 512 + cobase + 8];
        float* o0 = out + ((size_t)(b * 512 + cobase)) * 4096;
        float* o1 = o0 + 8 * 4096;
        #pragma unroll
        for (int nf = 0; nf < 16; nf++) {
            int px = wn * 128 + nf * 8 + (lane & 3) * 2;
            int ofs = (y0 + (px >> 6)) * 64 + (px & 63);
            *reinterpret_cast<float2*>(o0 + ofs) =
                make_float2(al0 * acc[mf][nf][0], al0 * acc[mf][nf][1]);
            *reinterpret_cast<float2*>(o1 + ofs) =
                make_float2(al1 * acc[mf][nf][2], al1 * acc[mf][nf][3]);
        }
    }
}

// ---------------- launch ----------------
extern "C" void kernel_launch(void* const* d_in, const int* in_sizes, int n_in,
                              void* d_out, int out_size) {
    const float* x     = (const float*)d_in[0];
    const float* style = (const float*)d_in[1];
    const float* weight= (const float*)d_in[2];
    const float* mw    = (const float*)d_in[3];
    const float* mbias = (const float*)d_in[4];
    float* out = (float*)d_out;
    (void)in_sizes; (void)n_in; (void)out_size;

    cudaFuncSetAttribute(conv_kernel, cudaFuncAttributeMaxDynamicSharedMemorySize, SMEM_BYTES);

    prepA_kernel<<<2048, 256>>>(style, mw, mbias, weight);
    prepB_kernel<<<1024 + 8192, 256>>>(x);
    conv_kernel<<<dim3(8, 8, 16), 256, SMEM_BYTES>>>(out);
}

// round 11
// speedup vs baseline: 1.1582x; 1.1006x over previous
#include <cuda_runtime.h>
#include <cuda_fp16.h>
#include <cstdint>

#define MOD_SCALE 0.04419417382415922f   /* 1/sqrt(512) */
#define CONV_SCALE 0.014731391274719739f /* 1/sqrt(512*9) */

// ---------------- device scratch ----------------
// Winograd F(2x2,3x3): 16 transform points, 16384 tiles (16 batch x 32 x 32), 512 ci/co.
__device__ float  g_s[16 * 512];
__device__ float  g_W2[512 * 512];
__device__ float  g_alpha[16 * 512];
__device__ __align__(16) __half g_U[16 * 512 * 512];          // [p][co][ci]   8.4 MB
__device__ __align__(16) __half g_V[134217728];               // [p][tile][ci] 268 MB
__device__ __align__(16) float  g_M[134217728];               // [p][co][tile] 536 MB

#define VPLANE 8388608   /* 16384*512 */
#define MPLANE 8388608   /* 512*16384 */

// ---------------- kernel A: mod s (blocks 0-1023) + weight transform U + W2 ----------------
__global__ void prepA_kernel(const float* __restrict__ style,
                             const float* __restrict__ mw,
                             const float* __restrict__ bias,
                             const float* __restrict__ weight) {
    if (blockIdx.x < 1024) {
        int warp = (blockIdx.x * 256 + threadIdx.x) >> 5;
        int lane = threadIdx.x & 31;
        int b = warp >> 9, ci = warp & 511;
        float sum = 0.f;
        const float* st = style + b * 512;
        const float* w  = mw + ci * 512;
        for (int d = lane; d < 512; d += 32) sum += st[d] * w[d];
        #pragma unroll
        for (int off = 16; off > 0; off >>= 1) sum += __shfl_xor_sync(0xffffffffu, sum, off);
        if (lane == 0) g_s[b * 512 + ci] = sum * MOD_SCALE + bias[ci];
    } else {
        int idx = (blockIdx.x - 1024) * 256 + threadIdx.x;  // co*512+ci
        const float* w = weight + (size_t)idx * 9;
        float g[3][3];
        float s2 = 0.f;
        #pragma unroll
        for (int k = 0; k < 9; k++) {
            float v = w[k];
            s2 += v * v;
            g[k / 3][k % 3] = v;
        }
        g_W2[idx] = s2;
        // T = G * g  (4x3), G = [[1,0,0],[.5,.5,.5],[.5,-.5,.5],[0,0,1]]
        float T[4][3];
        #pragma unroll
        for (int j = 0; j < 3; j++) {
            T[0][j] = g[0][j];
            T[1][j] = 0.5f * (g[0][j] + g[1][j] + g[2][j]);
            T[2][j] = 0.5f * (g[0][j] - g[1][j] + g[2][j]);
            T[3][j] = g[2][j];
        }
        // U = T * G^T (4x4)
        #pragma unroll
        for (int i = 0; i < 4; i++) {
            float u0 = T[i][0];
            float u1 = 0.5f * (T[i][0] + T[i][1] + T[i][2]);
            float u2 = 0.5f * (T[i][0] - T[i][1] + T[i][2]);
            float u3 = T[i][2];
            g_U[(size_t)(i * 4 + 0) * 262144 + idx] = __float2half(u0);
            g_U[(size_t)(i * 4 + 1) * 262144 + idx] = __float2half(u1);
            g_U[(size_t)(i * 4 + 2) * 262144 + idx] = __float2half(u2);
            g_U[(size_t)(i * 4 + 3) * 262144 + idx] = __float2half(u3);
        }
    }
}

// ---------------- kernel B: alpha (blocks 0-1023) + input transform V ----------------
// V blocks: one block per (b, ci-chunk of 32, ty): 32 tiles x 32 ci.
// Loads x (fp32 NCHW) rows 2ty-1..2ty+2 into smem [y][x+1][ci] (zero-padded borders),
// applies s[ci], computes B^T d B in fp32, stores fp16 to V[p][tile][ci].
__global__ void prepB_kernel(const float* __restrict__ x) {
    if (blockIdx.x < 1024) {
        int warp = (blockIdx.x * 256 + threadIdx.x) >> 5;
        int lane = threadIdx.x & 31;
        int b = warp >> 9, co = warp & 511;
        float sum = 0.f;
        const float* w2 = g_W2 + co * 512;
        const float* sv = g_s + b * 512;
        for (int ci = lane; ci < 512; ci += 32) {
            float s = sv[ci];
            sum += w2[ci] * s * s;
        }
        #pragma unroll
        for (int off = 16; off > 0; off >>= 1) sum += __shfl_xor_sync(0xffffffffu, sum, off);
        if (lane == 0)
            g_alpha[b * 512 + co] = CONV_SCALE / sqrtf(CONV_SCALE * CONV_SCALE * sum + 1e-8f);
        return;
    }
    __shared__ float smx[4][66][33];
    __shared__ float ss[32];
    int id = blockIdx.x - 1024;                 // 8192 blocks
    int ty = id & 31, ci0 = ((id >> 5) & 15) * 32, b = id >> 9;
    int tid = threadIdx.x;
    for (int k = tid; k < 4 * 66 * 33; k += 256) (&smx[0][0][0])[k] = 0.f;
    if (tid < 32) ss[tid] = g_s[b * 512 + ci0 + tid];
    __syncthreads();
    {
        int i = tid >> 3, r = tid & 7;          // ci-local, (yl, x-half)
        int yl = r >> 1, xh = (r & 1) * 32;
        int ygl = 2 * ty - 1 + yl;
        if (ygl >= 0 && ygl < 64) {
            float s = ss[i];
            const float4* src = reinterpret_cast<const float4*>(
                x + ((size_t)(b * 512 + ci0 + i) * 64 + ygl) * 64 + xh);
            #pragma unroll
            for (int k = 0; k < 8; k++) {
                float4 f = src[k];
                int c = xh + k * 4 + 1;
                smx[yl][c + 0][i] = f.x * s;
                smx[yl][c + 1][i] = f.y * s;
                smx[yl][c + 2][i] = f.z * s;
                smx[yl][c + 3][i] = f.w * s;
            }
        }
    }
    __syncthreads();
    int lane = tid & 31, w = tid >> 5;
    size_t tbase = ((size_t)(b * 32 + ty)) * 32;
    #pragma unroll
    for (int it = 0; it < 4; it++) {
        int tx = w + it * 8;
        float d[4][4];
        #pragma unroll
        for (int i = 0; i < 4; i++)
            #pragma unroll
            for (int j = 0; j < 4; j++)
                d[i][j] = smx[i][2 * tx + j][lane];
        // e = B^T d (rows), B^T = [[1,0,-1,0],[0,1,1,0],[0,-1,1,0],[0,1,0,-1]]
        float e[4][4];
        #pragma unroll
        for (int j = 0; j < 4; j++) {
            e[0][j] = d[0][j] - d[2][j];
            e[1][j] = d[1][j] + d[2][j];
            e[2][j] = d[2][j] - d[1][j];
            e[3][j] = d[1][j] - d[3][j];
        }
        size_t vofs = (tbase + tx) * 512 + ci0 + lane;
        #pragma unroll
        for (int i = 0; i < 4; i++) {
            float v0 = e[i][0] - e[i][2];
            float v1 = e[i][1] + e[i][2];
            float v2 = e[i][2] - e[i][1];
            float v3 = e[i][1] - e[i][3];
            g_V[(size_t)(i * 4 + 0) * VPLANE + vofs] = __float2half(v0);
            g_V[(size_t)(i * 4 + 1) * VPLANE + vofs] = __float2half(v1);
            g_V[(size_t)(i * 4 + 2) * VPLANE + vofs] = __float2half(v2);
            g_V[(size_t)(i * 4 + 3) * VPLANE + vofs] = __float2half(v3);
        }
    }
}

// ================= GEMM kernel: 16 points, M[p] = U[p] @ V[p]^T =================
// CTA: 128 co x 256 tiles, K-loop 4 stages of kc=128 ci. 8 warps = 4m x 2n,
// warp tile m32 x n128 (R8-proven fragment addressing, row stride 136 halfs = 272B).

#define GSTRIDE 136
#define GB_BYTES (256 * GSTRIDE * 2)   /* 69632 */
#define GA_BYTES (128 * GSTRIDE * 2)   /* 34816 */
#define GSTG (GB_BYTES + GA_BYTES)     /* 104448 */
#define GSMEM (2 * GSTG)               /* 208896 */

__device__ __forceinline__ void cp16(uint32_t dst, const void* src, int sz) {
    asm volatile("cp.async.cg.shared.global [%0], [%1], 16, %2;"
                 :: "r"(dst), "l"(src), "r"(sz) : "memory");
}
__device__ __forceinline__ void cp_commit() {
    asm volatile("cp.async.commit_group;" ::: "memory");
}
__device__ __forceinline__ void ldsm4(uint32_t r[4], uint32_t addr) {
    asm volatile("ldmatrix.sync.aligned.m8n8.x4.shared.b16 {%0,%1,%2,%3}, [%4];"
                 : "=r"(r[0]), "=r"(r[1]), "=r"(r[2]), "=r"(r[3]) : "r"(addr));
}
__device__ __forceinline__ void mma_f16(float acc[4], const uint32_t a[4], const uint32_t b2[2]) {
    asm volatile(
        "mma.sync.aligned.m16n8k16.row.col.f32.f16.f16.f32 "
        "{%0,%1,%2,%3}, {%4,%5,%6,%7}, {%8,%9}, {%0,%1,%2,%3};\n"
        : "+f"(acc[0]), "+f"(acc[1]), "+f"(acc[2]), "+f"(acc[3])
        : "r"(a[0]), "r"(a[1]), "r"(a[2]), "r"(a[3]), "r"(b2[0]), "r"(b2[1]));
}

__global__ void __launch_bounds__(256, 1) gemm_kernel() {
    extern __shared__ __align__(16) __half sh[];
    const uint32_t sbase = (uint32_t)__cvta_generic_to_shared(sh);

    const int tid = threadIdx.x, lane = tid & 31, warp = tid >> 5;
    const int wm = warp & 3, wn = warp >> 2;
    const int p = blockIdx.z, co0 = blockIdx.y * 128, n0 = blockIdx.x * 256;

    const __half* Vp = g_V + (size_t)p * VPLANE;
    const __half* Up = g_U + (size_t)p * 262144;

    // fill stage kc (128 ci) into buffer buf: B = V tiles (256 rows), A = U co (128 rows)
    auto fill = [&](int kc, int buf) {
        uint32_t bb_ = sbase + buf * GSTG;
        uint32_t ab_ = bb_ + GB_BYTES;
        int ofs = kc * 128;
        #pragma unroll
        for (int it = 0; it < 16; it++) {          // B: 256 rows x 16 cp
            int idx = tid + it * 256;
            int row = idx >> 4, v = idx & 15;
            cp16(bb_ + (uint32_t)(row * GSTRIDE + v * 8) * 2,
                 Vp + (size_t)(n0 + row) * 512 + ofs + v * 8, 16);
        }
        #pragma unroll
        for (int it = 0; it < 8; it++) {           // A: 128 rows x 16 cp
            int idx = tid + it * 256;
            int row = idx >> 4, v = idx & 15;
            cp16(ab_ + (uint32_t)(row * GSTRIDE + v * 8) * 2,
                 Up + (size_t)(co0 + row) * 512 + ofs + v * 8, 16);
        }
        cp_commit();
    };

    // ldmatrix lane bases (byte offsets, row stride 136 halfs = 272B)
    const int l15 = ((lane >> 3) & 1) * 8 + (lane & 7);
    const int aK  = (lane >> 4) * 8;
    uint32_t aBase[2];
    #pragma unroll
    for (int mf = 0; mf < 2; mf++)
        aBase[mf] = (uint32_t)(((wm * 32 + mf * 16 + l15) * GSTRIDE + aK) * 2);
    const int nloc = ((lane >> 4) & 1) * 8 + (lane & 7);
    const int bK   = ((lane >> 3) & 1) * 8;
    uint32_t bBase[8];
    #pragma unroll
    for (int nfp = 0; nfp < 8; nfp++)
        bBase[nfp] = (uint32_t)(((wn * 128 + nfp * 16 + nloc) * GSTRIDE + bK) * 2);

    float acc[2][16][4];
    #pragma unroll
    for (int mf = 0; mf < 2; mf++)
        #pragma unroll
        for (int nf = 0; nf < 16; nf++)
            #pragma unroll
            for (int i = 0; i < 4; i++) acc[mf][nf][i] = 0.f;

    fill(0, 0);
    fill(1, 1);

    for (int s = 0; s < 4; s++) {
        if (s < 3) asm volatile("cp.async.wait_group 1;" ::: "memory");
        else       asm volatile("cp.async.wait_group 0;" ::: "memory");
        __syncthreads();

        const uint32_t bB = sbase + (s & 1) * GSTG;
        const uint32_t aB = bB + GB_BYTES;

        #define AOFS(t, h) (aB + aBase[h] + (uint32_t)((t) * 32))
        #define BOFS(t, nfp) (bB + bBase[nfp] + (uint32_t)((t) * 32))

        uint32_t aa[2][2][4];
        uint32_t bb[2][4];
        ldsm4(aa[0][0], AOFS(0, 0));
        ldsm4(aa[0][1], AOFS(0, 1));
        ldsm4(bb[0], BOFS(0, 0));

        #pragma unroll
        for (int t = 0; t < 8; t++) {              // 8 k-steps of 16 ci
            const int ct = t & 1, nt = ct ^ 1;
            if (t < 7) {
                ldsm4(aa[nt][0], AOFS(t + 1, 0));
                ldsm4(aa[nt][1], AOFS(t + 1, 1));
            }
            #pragma unroll
            for (int nfp = 0; nfp < 8; nfp++) {
                const int cb = nfp & 1, nb = cb ^ 1;
                if (nfp < 7)     ldsm4(bb[nb], BOFS(t, nfp + 1));
                else if (t < 7)  ldsm4(bb[nb], BOFS(t + 1, 0));
                mma_f16(acc[0][2 * nfp],     aa[ct][0], bb[cb]);
                mma_f16(acc[0][2 * nfp + 1], aa[ct][0], bb[cb] + 2);
                mma_f16(acc[1][2 * nfp],     aa[ct][1], bb[cb]);
                mma_f16(acc[1][2 * nfp + 1], aa[ct][1], bb[cb] + 2);
            }
        }
        #undef AOFS
        #undef BOFS

        __syncthreads();
        if (s < 2) fill(s + 2, s & 1);
    }

    // epilogue: M[p][co][tile] fp32
    float* Mp = g_M + (size_t)p * MPLANE;
    #pragma unroll
    for (int mf = 0; mf < 2; mf++) {
        int co = co0 + wm * 32 + mf * 16 + (lane >> 2);
        float* m0 = Mp + (size_t)co * 16384;
        float* m1 = m0 + 8 * 16384;
        #pragma unroll
        for (int nf = 0; nf < 16; nf++) {
            int tile = n0 + wn * 128 + nf * 8 + (lane & 3) * 2;
            *reinterpret_cast<float2*>(m0 + tile) = make_float2(acc[mf][nf][0], acc[mf][nf][1]);
            *reinterpret_cast<float2*>(m1 + tile) = make_float2(acc[mf][nf][2], acc[mf][nf][3]);
        }
    }
}

// ---------------- output transform: y = A^T M A, scaled by alpha ----------------
__global__ void outT_kernel(float* __restrict__ out) {
    int id = blockIdx.x * 256 + threadIdx.x;    // 8.4M threads
    int tx = id & 31, ty = (id >> 5) & 31, b = (id >> 10) & 15, co = id >> 14;
    size_t mo = (size_t)co * 16384 + ((size_t)(b * 32 + ty)) * 32 + tx;
    float m[16];
    #pragma unroll
    for (int q = 0; q < 16; q++) m[q] = g_M[(size_t)q * MPLANE + mo];
    // s = A^T m (2x4), A^T = [[1,1,1,0],[0,1,-1,-1]]
    float s0[4], s1[4];
    #pragma unroll
    for (int j = 0; j < 4; j++) {
        s0[j] = m[j] + m[4 + j] + m[8 + j];
        s1[j] = m[4 + j] - m[8 + j] - m[12 + j];
    }
    float y00 = s0[0] + s0[1] + s0[2], y01 = s0[1] - s0[2] - s0[3];
    float y10 = s1[0] + s1[1] + s1[2], y11 = s1[1] - s1[2] - s1[3];
    float a = g_alpha[b * 512 + co];
    float* o = out + (((size_t)(b * 512 + co) * 64 + 2 * ty) * 64 + 2 * tx);
    *reinterpret_cast<float2*>(o)      = make_float2(a * y00, a * y01);
    *reinterpret_cast<float2*>(o + 64) = make_float2(a * y10, a * y11);
}

// ---------------- launch ----------------
extern "C" void kernel_launch(void* const* d_in, const int* in_sizes, int n_in,
                              void* d_out, int out_size) {
    const float* x     = (const float*)d_in[0];
    const float* style = (const float*)d_in[1];
    const float* weight= (const float*)d_in[2];
    const float* mw    = (const float*)d_in[3];
    const float* mbias = (const float*)d_in[4];
    float* out = (float*)d_out;
    (void)in_sizes; (void)n_in; (void)out_size;

    cudaFuncSetAttribute(gemm_kernel, cudaFuncAttributeMaxDynamicSharedMemorySize, GSMEM);

    prepA_kernel<<<2048, 256>>>(style, mw, mbias, weight);
    prepB_kernel<<<1024 + 8192, 256>>>(x);
    gemm_kernel<<<dim3(64, 4, 16), 256, GSMEM>>>();
    outT_kernel<<<32768, 256>>>(out);
}

// round 12
// speedup vs baseline: 1.1607x; 1.0022x over previous
#include <cuda_runtime.h>
#include <cuda_fp16.h>
#include <cstdint>

#define MOD_SCALE 0.04419417382415922f   /* 1/sqrt(512) */
#define CONV_SCALE 0.014731391274719739f /* 1/sqrt(512*9) */

// ---------------- device scratch ----------------
// Winograd F(2x2,3x3): 16 transform points, 16384 tiles (16 batch x 32 x 32), 512 ci/co.
__device__ float  g_s[16 * 512];
__device__ float  g_W2[512 * 512];
__device__ float  g_alpha[16 * 512];
__device__ __align__(16) __half g_U[16 * 512 * 512];          // [p][co][ci]   8.4 MB
__device__ __align__(16) __half g_V[134217728];               // [p][tile][ci] 268 MB
__device__ __align__(16) float  g_M[134217728];               // [p][co][tile] 536 MB

#define VPLANE 8388608   /* 16384*512 */
#define MPLANE 8388608   /* 512*16384 */

// ---------------- kernel A: mod s (blocks 0-1023) + weight transform U + W2 ----------------
__global__ void prepA_kernel(const float* __restrict__ style,
                             const float* __restrict__ mw,
                             const float* __restrict__ bias,
                             const float* __restrict__ weight) {
    if (blockIdx.x < 1024) {
        int warp = (blockIdx.x * 256 + threadIdx.x) >> 5;
        int lane = threadIdx.x & 31;
        int b = warp >> 9, ci = warp & 511;
        float sum = 0.f;
        const float* st = style + b * 512;
        const float* w  = mw + ci * 512;
        for (int d = lane; d < 512; d += 32) sum += st[d] * w[d];
        #pragma unroll
        for (int off = 16; off > 0; off >>= 1) sum += __shfl_xor_sync(0xffffffffu, sum, off);
        if (lane == 0) g_s[b * 512 + ci] = sum * MOD_SCALE + bias[ci];
    } else {
        int idx = (blockIdx.x - 1024) * 256 + threadIdx.x;  // co*512+ci
        const float* w = weight + (size_t)idx * 9;
        float g[3][3];
        float s2 = 0.f;
        #pragma unroll
        for (int k = 0; k < 9; k++) {
            float v = w[k];
            s2 += v * v;
            g[k / 3][k % 3] = v;
        }
        g_W2[idx] = s2;
        // T = G * g  (4x3), G = [[1,0,0],[.5,.5,.5],[.5,-.5,.5],[0,0,1]]
        float T[4][3];
        #pragma unroll
        for (int j = 0; j < 3; j++) {
            T[0][j] = g[0][j];
            T[1][j] = 0.5f * (g[0][j] + g[1][j] + g[2][j]);
            T[2][j] = 0.5f * (g[0][j] - g[1][j] + g[2][j]);
            T[3][j] = g[2][j];
        }
        // U = T * G^T (4x4)
        #pragma unroll
        for (int i = 0; i < 4; i++) {
            float u0 = T[i][0];
            float u1 = 0.5f * (T[i][0] + T[i][1] + T[i][2]);
            float u2 = 0.5f * (T[i][0] - T[i][1] + T[i][2]);
            float u3 = T[i][2];
            g_U[(size_t)(i * 4 + 0) * 262144 + idx] = __float2half(u0);
            g_U[(size_t)(i * 4 + 1) * 262144 + idx] = __float2half(u1);
            g_U[(size_t)(i * 4 + 2) * 262144 + idx] = __float2half(u2);
            g_U[(size_t)(i * 4 + 3) * 262144 + idx] = __float2half(u3);
        }
    }
}

// ---------------- kernel B: alpha (blocks 0-1023) + input transform V ----------------
__global__ void prepB_kernel(const float* __restrict__ x) {
    if (blockIdx.x < 1024) {
        int warp = (blockIdx.x * 256 + threadIdx.x) >> 5;
        int lane = threadIdx.x & 31;
        int b = warp >> 9, co = warp & 511;
        float sum = 0.f;
        const float* w2 = g_W2 + co * 512;
        const float* sv = g_s + b * 512;
        for (int ci = lane; ci < 512; ci += 32) {
            float s = sv[ci];
            sum += w2[ci] * s * s;
        }
        #pragma unroll
        for (int off = 16; off > 0; off >>= 1) sum += __shfl_xor_sync(0xffffffffu, sum, off);
        if (lane == 0)
            g_alpha[b * 512 + co] = CONV_SCALE / sqrtf(CONV_SCALE * CONV_SCALE * sum + 1e-8f);
        return;
    }
    __shared__ float smx[4][66][33];
    __shared__ float ss[32];
    int id = blockIdx.x - 1024;                 // 8192 blocks
    int ty = id & 31, ci0 = ((id >> 5) & 15) * 32, b = id >> 9;
    int tid = threadIdx.x;
    for (int k = tid; k < 4 * 66 * 33; k += 256) (&smx[0][0][0])[k] = 0.f;
    if (tid < 32) ss[tid] = g_s[b * 512 + ci0 + tid];
    __syncthreads();
    {
        int i = tid >> 3, r = tid & 7;          // ci-local, (yl, x-half)
        int yl = r >> 1, xh = (r & 1) * 32;
        int ygl = 2 * ty - 1 + yl;
        if (ygl >= 0 && ygl < 64) {
            float s = ss[i];
            const float4* src = reinterpret_cast<const float4*>(
                x + ((size_t)(b * 512 + ci0 + i) * 64 + ygl) * 64 + xh);
            #pragma unroll
            for (int k = 0; k < 8; k++) {
                float4 f = src[k];
                int c = xh + k * 4 + 1;
                smx[yl][c + 0][i] = f.x * s;
                smx[yl][c + 1][i] = f.y * s;
                smx[yl][c + 2][i] = f.z * s;
                smx[yl][c + 3][i] = f.w * s;
            }
        }
    }
    __syncthreads();
    int lane = tid & 31, w = tid >> 5;
    size_t tbase = ((size_t)(b * 32 + ty)) * 32;
    #pragma unroll
    for (int it = 0; it < 4; it++) {
        int tx = w + it * 8;
        float d[4][4];
        #pragma unroll
        for (int i = 0; i < 4; i++)
            #pragma unroll
            for (int j = 0; j < 4; j++)
                d[i][j] = smx[i][2 * tx + j][lane];
        float e[4][4];
        #pragma unroll
        for (int j = 0; j < 4; j++) {
            e[0][j] = d[0][j] - d[2][j];
            e[1][j] = d[1][j] + d[2][j];
            e[2][j] = d[2][j] - d[1][j];
            e[3][j] = d[1][j] - d[3][j];
        }
        size_t vofs = (tbase + tx) * 512 + ci0 + lane;
        #pragma unroll
        for (int i = 0; i < 4; i++) {
            float v0 = e[i][0] - e[i][2];
            float v1 = e[i][1] + e[i][2];
            float v2 = e[i][2] - e[i][1];
            float v3 = e[i][1] - e[i][3];
            g_V[(size_t)(i * 4 + 0) * VPLANE + vofs] = __float2half(v0);
            g_V[(size_t)(i * 4 + 1) * VPLANE + vofs] = __float2half(v1);
            g_V[(size_t)(i * 4 + 2) * VPLANE + vofs] = __float2half(v2);
            g_V[(size_t)(i * 4 + 3) * VPLANE + vofs] = __float2half(v3);
        }
    }
}

// ================= GEMM kernel: 16 points, M[p] = U[p] @ V[p]^T =================
// CTA: 128 co x 256 tiles, K-loop 4 stages of kc=128 ci. 8 warps = 4m x 2n.
// Grid: x = co-tile (fastest) so the 4 CTAs sharing an n-tile's V chunk are
// co-resident -> V served from L2, DRAM V traffic ~1x instead of 4x.

#define GSTRIDE 136
#define GB_BYTES (256 * GSTRIDE * 2)   /* 69632 */
#define GA_BYTES (128 * GSTRIDE * 2)   /* 34816 */
#define GSTG (GB_BYTES + GA_BYTES)     /* 104448 */
#define GSMEM (2 * GSTG)               /* 208896 */

__device__ __forceinline__ void cp16(uint32_t dst, const void* src, int sz) {
    asm volatile("cp.async.cg.shared.global [%0], [%1], 16, %2;"
                 :: "r"(dst), "l"(src), "r"(sz) : "memory");
}
__device__ __forceinline__ void cp_commit() {
    asm volatile("cp.async.commit_group;" ::: "memory");
}
__device__ __forceinline__ void ldsm4(uint32_t r[4], uint32_t addr) {
    asm volatile("ldmatrix.sync.aligned.m8n8.x4.shared.b16 {%0,%1,%2,%3}, [%4];"
                 : "=r"(r[0]), "=r"(r[1]), "=r"(r[2]), "=r"(r[3]) : "r"(addr));
}
__device__ __forceinline__ void mma_f16(float acc[4], const uint32_t a[4], const uint32_t b2[2]) {
    asm volatile(
        "mma.sync.aligned.m16n8k16.row.col.f32.f16.f16.f32 "
        "{%0,%1,%2,%3}, {%4,%5,%6,%7}, {%8,%9}, {%0,%1,%2,%3};\n"
        : "+f"(acc[0]), "+f"(acc[1]), "+f"(acc[2]), "+f"(acc[3])
        : "r"(a[0]), "r"(a[1]), "r"(a[2]), "r"(a[3]), "r"(b2[0]), "r"(b2[1]));
}

__global__ void __launch_bounds__(256, 1) gemm_kernel() {
    extern __shared__ __align__(16) __half sh[];
    const uint32_t sbase = (uint32_t)__cvta_generic_to_shared(sh);

    const int tid = threadIdx.x, lane = tid & 31, warp = tid >> 5;
    const int wm = warp & 3, wn = warp >> 2;
    const int p = blockIdx.z, co0 = blockIdx.x * 128, n0 = blockIdx.y * 256;

    const __half* Vp = g_V + (size_t)p * VPLANE;
    const __half* Up = g_U + (size_t)p * 262144;

    auto fill = [&](int kc, int buf) {
        uint32_t bb_ = sbase + buf * GSTG;
        uint32_t ab_ = bb_ + GB_BYTES;
        int ofs = kc * 128;
        #pragma unroll
        for (int it = 0; it < 16; it++) {          // B: 256 rows x 16 cp
            int idx = tid + it * 256;
            int row = idx >> 4, v = idx & 15;
            cp16(bb_ + (uint32_t)(row * GSTRIDE + v * 8) * 2,
                 Vp + (size_t)(n0 + row) * 512 + ofs + v * 8, 16);
        }
        #pragma unroll
        for (int it = 0; it < 8; it++) {           // A: 128 rows x 16 cp
            int idx = tid + it * 256;
            int row = idx >> 4, v = idx & 15;
            cp16(ab_ + (uint32_t)(row * GSTRIDE + v * 8) * 2,
                 Up + (size_t)(co0 + row) * 512 + ofs + v * 8, 16);
        }
        cp_commit();
    };

    const int l15 = ((lane >> 3) & 1) * 8 + (lane & 7);
    const int aK  = (lane >> 4) * 8;
    uint32_t aBase[2];
    #pragma unroll
    for (int mf = 0; mf < 2; mf++)
        aBase[mf] = (uint32_t)(((wm * 32 + mf * 16 + l15) * GSTRIDE + aK) * 2);
    const int nloc = ((lane >> 4) & 1) * 8 + (lane & 7);
    const int bK   = ((lane >> 3) & 1) * 8;
    uint32_t bBase[8];
    #pragma unroll
    for (int nfp = 0; nfp < 8; nfp++)
        bBase[nfp] = (uint32_t)(((wn * 128 + nfp * 16 + nloc) * GSTRIDE + bK) * 2);

    float acc[2][16][4];
    #pragma unroll
    for (int mf = 0; mf < 2; mf++)
        #pragma unroll
        for (int nf = 0; nf < 16; nf++)
            #pragma unroll
            for (int i = 0; i < 4; i++) acc[mf][nf][i] = 0.f;

    fill(0, 0);
    fill(1, 1);

    for (int s = 0; s < 4; s++) {
        if (s < 3) asm volatile("cp.async.wait_group 1;" ::: "memory");
        else       asm volatile("cp.async.wait_group 0;" ::: "memory");
        __syncthreads();

        const uint32_t bB = sbase + (s & 1) * GSTG;
        const uint32_t aB = bB + GB_BYTES;

        #define AOFS(t, h) (aB + aBase[h] + (uint32_t)((t) * 32))
        #define BOFS(t, nfp) (bB + bBase[nfp] + (uint32_t)((t) * 32))

        uint32_t aa[2][2][4];
        uint32_t bb[2][4];
        ldsm4(aa[0][0], AOFS(0, 0));
        ldsm4(aa[0][1], AOFS(0, 1));
        ldsm4(bb[0], BOFS(0, 0));

        #pragma unroll
        for (int t = 0; t < 8; t++) {              // 8 k-steps of 16 ci
            const int ct = t & 1, nt = ct ^ 1;
            if (t < 7) {
                ldsm4(aa[nt][0], AOFS(t + 1, 0));
                ldsm4(aa[nt][1], AOFS(t + 1, 1));
            }
            #pragma unroll
            for (int nfp = 0; nfp < 8; nfp++) {
                const int cb = nfp & 1, nb = cb ^ 1;
                if (nfp < 7)     ldsm4(bb[nb], BOFS(t, nfp + 1));
                else if (t < 7)  ldsm4(bb[nb], BOFS(t + 1, 0));
                mma_f16(acc[0][2 * nfp],     aa[ct][0], bb[cb]);
                mma_f16(acc[0][2 * nfp + 1], aa[ct][0], bb[cb] + 2);
                mma_f16(acc[1][2 * nfp],     aa[ct][1], bb[cb]);
                mma_f16(acc[1][2 * nfp + 1], aa[ct][1], bb[cb] + 2);
            }
        }
        #undef AOFS
        #undef BOFS

        __syncthreads();
        if (s < 2) fill(s + 2, s & 1);
    }

    // epilogue: M[p][co][tile] fp32
    float* Mp = g_M + (size_t)p * MPLANE;
    #pragma unroll
    for (int mf = 0; mf < 2; mf++) {
        int co = co0 + wm * 32 + mf * 16 + (lane >> 2);
        float* m0 = Mp + (size_t)co * 16384;
        float* m1 = m0 + 8 * 16384;
        #pragma unroll
        for (int nf = 0; nf < 16; nf++) {
            int tile = n0 + wn * 128 + nf * 8 + (lane & 3) * 2;
            *reinterpret_cast<float2*>(m0 + tile) = make_float2(acc[mf][nf][0], acc[mf][nf][1]);
            *reinterpret_cast<float2*>(m1 + tile) = make_float2(acc[mf][nf][2], acc[mf][nf][3]);
        }
    }
}

// ---------------- output transform: y = A^T M A, scaled by alpha ----------------
__global__ void outT_kernel(float* __restrict__ out) {
    int id = blockIdx.x * 256 + threadIdx.x;    // 8.4M threads
    int tx = id & 31, ty = (id >> 5) & 31, b = (id >> 10) & 15, co = id >> 14;
    size_t mo = (size_t)co * 16384 + ((size_t)(b * 32 + ty)) * 32 + tx;
    float m[16];
    #pragma unroll
    for (int q = 0; q < 16; q++) m[q] = g_M[(size_t)q * MPLANE + mo];
    float s0[4], s1[4];
    #pragma unroll
    for (int j = 0; j < 4; j++) {
        s0[j] = m[j] + m[4 + j] + m[8 + j];
        s1[j] = m[4 + j] - m[8 + j] - m[12 + j];
    }
    float y00 = s0[0] + s0[1] + s0[2], y01 = s0[1] - s0[2] - s0[3];
    float y10 = s1[0] + s1[1] + s1[2], y11 = s1[1] - s1[2] - s1[3];
    float a = g_alpha[b * 512 + co];
    float* o = out + (((size_t)(b * 512 + co) * 64 + 2 * ty) * 64 + 2 * tx);
    *reinterpret_cast<float2*>(o)      = make_float2(a * y00, a * y01);
    *reinterpret_cast<float2*>(o + 64) = make_float2(a * y10, a * y11);
}

// ---------------- launch ----------------
extern "C" void kernel_launch(void* const* d_in, const int* in_sizes, int n_in,
                              void* d_out, int out_size) {
    const float* x     = (const float*)d_in[0];
    const float* style = (const float*)d_in[1];
    const float* weight= (const float*)d_in[2];
    const float* mw    = (const float*)d_in[3];
    const float* mbias = (const float*)d_in[4];
    float* out = (float*)d_out;
    (void)in_sizes; (void)n_in; (void)out_size;

    cudaFuncSetAttribute(gemm_kernel, cudaFuncAttributeMaxDynamicSharedMemorySize, GSMEM);

    prepA_kernel<<<2048, 256>>>(style, mw, mbias, weight);
    prepB_kernel<<<1024 + 8192, 256>>>(x);
    gemm_kernel<<<dim3(4, 64, 16), 256, GSMEM>>>();
    outT_kernel<<<32768, 256>>>(out);
}

// round 13
// speedup vs baseline: 1.2388x; 1.0673x over previous
#include <cuda_runtime.h>
#include <cuda_fp16.h>
#include <cstdint>

#define MOD_SCALE 0.04419417382415922f   /* 1/sqrt(512) */
#define CONV_SCALE 0.014731391274719739f /* 1/sqrt(512*9) */

// ---------------- device scratch ----------------
// Winograd F(2x2,3x3): 16 transform points, 16384 tiles (16 batch x 32 x 32), 512 ci/co.
__device__ float  g_s[16 * 512];
__device__ float  g_W2[512 * 512];
__device__ float  g_alpha[16 * 512];
__device__ __align__(16) __half g_U[16 * 512 * 512];          // [p][co][ci]   8.4 MB
__device__ __align__(16) __half g_V[134217728];               // [p][tile][ci] 268 MB
__device__ __align__(16) __half g_M[134217728];               // [p][co][tile] 268 MB (fp16)

#define VPLANE 8388608   /* 16384*512 */
#define MPLANE 8388608   /* 512*16384 */

// ---------------- kernel A: mod s (blocks 0-1023) + weight transform U + W2 ----------------
__global__ void prepA_kernel(const float* __restrict__ style,
                             const float* __restrict__ mw,
                             const float* __restrict__ bias,
                             const float* __restrict__ weight) {
    if (blockIdx.x < 1024) {
        int warp = (blockIdx.x * 256 + threadIdx.x) >> 5;
        int lane = threadIdx.x & 31;
        int b = warp >> 9, ci = warp & 511;
        float sum = 0.f;
        const float* st = style + b * 512;
        const float* w  = mw + ci * 512;
        for (int d = lane; d < 512; d += 32) sum += st[d] * w[d];
        #pragma unroll
        for (int off = 16; off > 0; off >>= 1) sum += __shfl_xor_sync(0xffffffffu, sum, off);
        if (lane == 0) g_s[b * 512 + ci] = sum * MOD_SCALE + bias[ci];
    } else {
        int idx = (blockIdx.x - 1024) * 256 + threadIdx.x;  // co*512+ci
        const float* w = weight + (size_t)idx * 9;
        float g[3][3];
        float s2 = 0.f;
        #pragma unroll
        for (int k = 0; k < 9; k++) {
            float v = w[k];
            s2 += v * v;
            g[k / 3][k % 3] = v;
        }
        g_W2[idx] = s2;
        float T[4][3];
        #pragma unroll
        for (int j = 0; j < 3; j++) {
            T[0][j] = g[0][j];
            T[1][j] = 0.5f * (g[0][j] + g[1][j] + g[2][j]);
            T[2][j] = 0.5f * (g[0][j] - g[1][j] + g[2][j]);
            T[3][j] = g[2][j];
        }
        #pragma unroll
        for (int i = 0; i < 4; i++) {
            float u0 = T[i][0];
            float u1 = 0.5f * (T[i][0] + T[i][1] + T[i][2]);
            float u2 = 0.5f * (T[i][0] - T[i][1] + T[i][2]);
            float u3 = T[i][2];
            g_U[(size_t)(i * 4 + 0) * 262144 + idx] = __float2half(u0);
            g_U[(size_t)(i * 4 + 1) * 262144 + idx] = __float2half(u1);
            g_U[(size_t)(i * 4 + 2) * 262144 + idx] = __float2half(u2);
            g_U[(size_t)(i * 4 + 3) * 262144 + idx] = __float2half(u3);
        }
    }
}

// ---------------- kernel B: alpha (blocks 0-1023) + input transform V ----------------
__global__ void prepB_kernel(const float* __restrict__ x) {
    if (blockIdx.x < 1024) {
        int warp = (blockIdx.x * 256 + threadIdx.x) >> 5;
        int lane = threadIdx.x & 31;
        int b = warp >> 9, co = warp & 511;
        float sum = 0.f;
        const float* w2 = g_W2 + co * 512;
        const float* sv = g_s + b * 512;
        for (int ci = lane; ci < 512; ci += 32) {
            float s = sv[ci];
            sum += w2[ci] * s * s;
        }
        #pragma unroll
        for (int off = 16; off > 0; off >>= 1) sum += __shfl_xor_sync(0xffffffffu, sum, off);
        if (lane == 0)
            g_alpha[b * 512 + co] = CONV_SCALE / sqrtf(CONV_SCALE * CONV_SCALE * sum + 1e-8f);
        return;
    }
    __shared__ float smx[4][66][33];
    __shared__ float ss[32];
    int id = blockIdx.x - 1024;                 // 8192 blocks
    int ty = id & 31, ci0 = ((id >> 5) & 15) * 32, b = id >> 9;
    int tid = threadIdx.x;
    for (int k = tid; k < 4 * 66 * 33; k += 256) (&smx[0][0][0])[k] = 0.f;
    if (tid < 32) ss[tid] = g_s[b * 512 + ci0 + tid];
    __syncthreads();
    {
        int i = tid >> 3, r = tid & 7;
        int yl = r >> 1, xh = (r & 1) * 32;
        int ygl = 2 * ty - 1 + yl;
        if (ygl >= 0 && ygl < 64) {
            float s = ss[i];
            const float4* src = reinterpret_cast<const float4*>(
                x + ((size_t)(b * 512 + ci0 + i) * 64 + ygl) * 64 + xh);
            #pragma unroll
            for (int k = 0; k < 8; k++) {
                float4 f = src[k];
                int c = xh + k * 4 + 1;
                smx[yl][c + 0][i] = f.x * s;
                smx[yl][c + 1][i] = f.y * s;
                smx[yl][c + 2][i] = f.z * s;
                smx[yl][c + 3][i] = f.w * s;
            }
        }
    }
    __syncthreads();
    int lane = tid & 31, w = tid >> 5;
    size_t tbase = ((size_t)(b * 32 + ty)) * 32;
    #pragma unroll
    for (int it = 0; it < 4; it++) {
        int tx = w + it * 8;
        float d[4][4];
        #pragma unroll
        for (int i = 0; i < 4; i++)
            #pragma unroll
            for (int j = 0; j < 4; j++)
                d[i][j] = smx[i][2 * tx + j][lane];
        float e[4][4];
        #pragma unroll
        for (int j = 0; j < 4; j++) {
            e[0][j] = d[0][j] - d[2][j];
            e[1][j] = d[1][j] + d[2][j];
            e[2][j] = d[2][j] - d[1][j];
            e[3][j] = d[1][j] - d[3][j];
        }
        size_t vofs = (tbase + tx) * 512 + ci0 + lane;
        #pragma unroll
        for (int i = 0; i < 4; i++) {
            float v0 = e[i][0] - e[i][2];
            float v1 = e[i][1] + e[i][2];
            float v2 = e[i][2] - e[i][1];
            float v3 = e[i][1] - e[i][3];
            g_V[(size_t)(i * 4 + 0) * VPLANE + vofs] = __float2half(v0);
            g_V[(size_t)(i * 4 + 1) * VPLANE + vofs] = __float2half(v1);
            g_V[(size_t)(i * 4 + 2) * VPLANE + vofs] = __float2half(v2);
            g_V[(size_t)(i * 4 + 3) * VPLANE + vofs] = __float2half(v3);
        }
    }
}

// ================= GEMM kernel: 16 points, M[p] = U[p] @ V[p]^T (fp16 M) =================
#define GSTRIDE 136
#define GB_BYTES (256 * GSTRIDE * 2)   /* 69632 */
#define GA_BYTES (128 * GSTRIDE * 2)   /* 34816 */
#define GSTG (GB_BYTES + GA_BYTES)     /* 104448 */
#define GSMEM (2 * GSTG)               /* 208896 */

__device__ __forceinline__ void cp16(uint32_t dst, const void* src, int sz) {
    asm volatile("cp.async.cg.shared.global [%0], [%1], 16, %2;"
                 :: "r"(dst), "l"(src), "r"(sz) : "memory");
}
__device__ __forceinline__ void cp_commit() {
    asm volatile("cp.async.commit_group;" ::: "memory");
}
__device__ __forceinline__ void ldsm4(uint32_t r[4], uint32_t addr) {
    asm volatile("ldmatrix.sync.aligned.m8n8.x4.shared.b16 {%0,%1,%2,%3}, [%4];"
                 : "=r"(r[0]), "=r"(r[1]), "=r"(r[2]), "=r"(r[3]) : "r"(addr));
}
__device__ __forceinline__ void mma_f16(float acc[4], const uint32_t a[4], const uint32_t b2[2]) {
    asm volatile(
        "mma.sync.aligned.m16n8k16.row.col.f32.f16.f16.f32 "
        "{%0,%1,%2,%3}, {%4,%5,%6,%7}, {%8,%9}, {%0,%1,%2,%3};\n"
        : "+f"(acc[0]), "+f"(acc[1]), "+f"(acc[2]), "+f"(acc[3])
        : "r"(a[0]), "r"(a[1]), "r"(a[2]), "r"(a[3]), "r"(b2[0]), "r"(b2[1]));
}

__global__ void __launch_bounds__(256, 1) gemm_kernel() {
    extern __shared__ __align__(16) __half sh[];
    const uint32_t sbase = (uint32_t)__cvta_generic_to_shared(sh);

    const int tid = threadIdx.x, lane = tid & 31, warp = tid >> 5;
    const int wm = warp & 3, wn = warp >> 2;
    const int p = blockIdx.z, co0 = blockIdx.x * 128, n0 = blockIdx.y * 256;

    const __half* Vp = g_V + (size_t)p * VPLANE;
    const __half* Up = g_U + (size_t)p * 262144;

    auto fill = [&](int kc, int buf) {
        uint32_t bb_ = sbase + buf * GSTG;
        uint32_t ab_ = bb_ + GB_BYTES;
        int ofs = kc * 128;
        #pragma unroll
        for (int it = 0; it < 16; it++) {
            int idx = tid + it * 256;
            int row = idx >> 4, v = idx & 15;
            cp16(bb_ + (uint32_t)(row * GSTRIDE + v * 8) * 2,
                 Vp + (size_t)(n0 + row) * 512 + ofs + v * 8, 16);
        }
        #pragma unroll
        for (int it = 0; it < 8; it++) {
            int idx = tid + it * 256;
            int row = idx >> 4, v = idx & 15;
            cp16(ab_ + (uint32_t)(row * GSTRIDE + v * 8) * 2,
                 Up + (size_t)(co0 + row) * 512 + ofs + v * 8, 16);
        }
        cp_commit();
    };

    const int l15 = ((lane >> 3) & 1) * 8 + (lane & 7);
    const int aK  = (lane >> 4) * 8;
    uint32_t aBase[2];
    #pragma unroll
    for (int mf = 0; mf < 2; mf++)
        aBase[mf] = (uint32_t)(((wm * 32 + mf * 16 + l15) * GSTRIDE + aK) * 2);
    const int nloc = ((lane >> 4) & 1) * 8 + (lane & 7);
    const int bK   = ((lane >> 3) & 1) * 8;
    uint32_t bBase[8];
    #pragma unroll
    for (int nfp = 0; nfp < 8; nfp++)
        bBase[nfp] = (uint32_t)(((wn * 128 + nfp * 16 + nloc) * GSTRIDE + bK) * 2);

    float acc[2][16][4];
    #pragma unroll
    for (int mf = 0; mf < 2; mf++)
        #pragma unroll
        for (int nf = 0; nf < 16; nf++)
            #pragma unroll
            for (int i = 0; i < 4; i++) acc[mf][nf][i] = 0.f;

    fill(0, 0);
    fill(1, 1);

    for (int s = 0; s < 4; s++) {
        if (s < 3) asm volatile("cp.async.wait_group 1;" ::: "memory");
        else       asm volatile("cp.async.wait_group 0;" ::: "memory");
        __syncthreads();

        const uint32_t bB = sbase + (s & 1) * GSTG;
        const uint32_t aB = bB + GB_BYTES;

        #define AOFS(t, h) (aB + aBase[h] + (uint32_t)((t) * 32))
        #define BOFS(t, nfp) (bB + bBase[nfp] + (uint32_t)((t) * 32))

        uint32_t aa[2][2][4];
        uint32_t bb[2][4];
        ldsm4(aa[0][0], AOFS(0, 0));
        ldsm4(aa[0][1], AOFS(0, 1));
        ldsm4(bb[0], BOFS(0, 0));

        #pragma unroll
        for (int t = 0; t < 8; t++) {
            const int ct = t & 1, nt = ct ^ 1;
            if (t < 7) {
                ldsm4(aa[nt][0], AOFS(t + 1, 0));
                ldsm4(aa[nt][1], AOFS(t + 1, 1));
            }
            #pragma unroll
            for (int nfp = 0; nfp < 8; nfp++) {
                const int cb = nfp & 1, nb = cb ^ 1;
                if (nfp < 7)     ldsm4(bb[nb], BOFS(t, nfp + 1));
                else if (t < 7)  ldsm4(bb[nb], BOFS(t + 1, 0));
                mma_f16(acc[0][2 * nfp],     aa[ct][0], bb[cb]);
                mma_f16(acc[0][2 * nfp + 1], aa[ct][0], bb[cb] + 2);
                mma_f16(acc[1][2 * nfp],     aa[ct][1], bb[cb]);
                mma_f16(acc[1][2 * nfp + 1], aa[ct][1], bb[cb] + 2);
            }
        }
        #undef AOFS
        #undef BOFS

        __syncthreads();
        if (s < 2) fill(s + 2, s & 1);
    }

    // epilogue: M[p][co][tile] fp16 (half2 stores, half write traffic)
    __half* Mp = g_M + (size_t)p * MPLANE;
    #pragma unroll
    for (int mf = 0; mf < 2; mf++) {
        int co = co0 + wm * 32 + mf * 16 + (lane >> 2);
        __half* m0 = Mp + (size_t)co * 16384;
        __half* m1 = m0 + 8 * 16384;
        #pragma unroll
        for (int nf = 0; nf < 16; nf++) {
            int tile = n0 + wn * 128 + nf * 8 + (lane & 3) * 2;
            *reinterpret_cast<__half2*>(m0 + tile) =
                __floats2half2_rn(acc[mf][nf][0], acc[mf][nf][1]);
            *reinterpret_cast<__half2*>(m1 + tile) =
                __floats2half2_rn(acc[mf][nf][2], acc[mf][nf][3]);
        }
    }
}

// ---------------- output transform: y = A^T M A (fp16 M, tile-pairs via half2) ----------------
__global__ void outT_kernel(float* __restrict__ out) {
    int id = blockIdx.x * 256 + threadIdx.x;    // 4.2M threads (tile pairs)
    int txp = id & 15, ty = (id >> 4) & 31, b = (id >> 9) & 15, co = id >> 13;
    size_t mo = (size_t)co * 16384 + ((size_t)(b * 32 + ty)) * 32 + 2 * txp;
    float2 m[16];
    #pragma unroll
    for (int q = 0; q < 16; q++)
        m[q] = __half22float2(*reinterpret_cast<const __half2*>(g_M + (size_t)q * MPLANE + mo));
    float a = g_alpha[b * 512 + co];
    float4 row0, row1;
    {   // tile A (.x lane)
        float s0[4], s1[4];
        #pragma unroll
        for (int j = 0; j < 4; j++) {
            s0[j] = m[j].x + m[4 + j].x + m[8 + j].x;
            s1[j] = m[4 + j].x - m[8 + j].x - m[12 + j].x;
        }
        row0.x = a * (s0[0] + s0[1] + s0[2]); row0.y = a * (s0[1] - s0[2] - s0[3]);
        row1.x = a * (s1[0] + s1[1] + s1[2]); row1.y = a * (s1[1] - s1[2] - s1[3]);
    }
    {   // tile B (.y lane)
        float s0[4], s1[4];
        #pragma unroll
        for (int j = 0; j < 4; j++) {
            s0[j] = m[j].y + m[4 + j].y + m[8 + j].y;
            s1[j] = m[4 + j].y - m[8 + j].y - m[12 + j].y;
        }
        row0.z = a * (s0[0] + s0[1] + s0[2]); row0.w = a * (s0[1] - s0[2] - s0[3]);
        row1.z = a * (s1[0] + s1[1] + s1[2]); row1.w = a * (s1[1] - s1[2] - s1[3]);
    }
    float* o = out + (((size_t)(b * 512 + co) * 64 + 2 * ty) * 64 + 4 * txp);
    *reinterpret_cast<float4*>(o)      = row0;
    *reinterpret_cast<float4*>(o + 64) = row1;
}

// ---------------- launch ----------------
extern "C" void kernel_launch(void* const* d_in, const int* in_sizes, int n_in,
                              void* d_out, int out_size) {
    const float* x     = (const float*)d_in[0];
    const float* style = (const float*)d_in[1];
    const float* weight= (const float*)d_in[2];
    const float* mw    = (const float*)d_in[3];
    const float* mbias = (const float*)d_in[4];
    float* out = (float*)d_out;
    (void)in_sizes; (void)n_in; (void)out_size;

    cudaFuncSetAttribute(gemm_kernel, cudaFuncAttributeMaxDynamicSharedMemorySize, GSMEM);

    prepA_kernel<<<2048, 256>>>(style, mw, mbias, weight);
    prepB_kernel<<<1024 + 8192, 256>>>(x);
    gemm_kernel<<<dim3(4, 64, 16), 256, GSMEM>>>();
    outT_kernel<<<16384, 256>>>(out);
}